// round 5
// baseline (speedup 1.0000x reference)
#include <cuda_runtime.h>
#include <math.h>

#define Bsz 1024
#define Nn  100
#define Hh  256
#define H3  768
#define NBLK 128

// ---------------- static device scratch ----------------
__device__ float g_G[Bsz*Nn*H3];      // enc @ W1T + b_ih1
__device__ float g_ref[Bsz*Nn*Hh];    // enc @ W_ref
__device__ float g_G0[Bsz*H3];
__device__ float g_mean[Bsz*Hh];
__device__ float g_W1T[Hh*H3];        // [k][j] for precompute GEMM
__device__ float g_W2P[H3*Hh];        // [ct][jj][k]  (4 x 192 x 256)
__device__ float g_WqT[Hh*Hh];        // [j][k]
__device__ float g_bias0[H3];
__device__ float g_wD[H3];
__device__ float g_h1[Bsz*Hh];
__device__ float g_h2[Bsz*Hh];
__device__ float g_q[Bsz*Hh];
__device__ unsigned g_cnt = 0;
__device__ volatile unsigned g_gen = 0;

// ---------------- math helpers ----------------
__device__ __forceinline__ float fast_tanh(float x) {
    float ax = fabsf(x);
    float e  = __expf(-2.0f * ax);
    float t  = __fdividef(1.0f - e, 1.0f + e);
    return copysignf(t, x);
}
__device__ __forceinline__ float sigmoidf_(float x) {
    return __fdividef(1.0f, 1.0f + __expf(-x));
}
__device__ __forceinline__ float tanh4dot(float4 q, float4 r, float4 v) {
    const float C = -2.8853900817779268f;   // -2*log2(e)
    float x0=q.x+r.x, x1=q.y+r.y, x2=q.z+r.z, x3=q.w+r.w;
    float e0=exp2f(fabsf(x0)*C), e1=exp2f(fabsf(x1)*C);
    float e2=exp2f(fabsf(x2)*C), e3=exp2f(fabsf(x3)*C);
    float a0=1.f+e0, a1=1.f+e1, a2=1.f+e2, a3=1.f+e3;
    float m0=(1.f-e0)*v.x, m1=(1.f-e1)*v.y, m2=(1.f-e2)*v.z, m3=(1.f-e3)*v.w;
    m0=__uint_as_float(__float_as_uint(m0)^(__float_as_uint(x0)&0x80000000u));
    m1=__uint_as_float(__float_as_uint(m1)^(__float_as_uint(x1)&0x80000000u));
    m2=__uint_as_float(__float_as_uint(m2)^(__float_as_uint(x2)&0x80000000u));
    m3=__uint_as_float(__float_as_uint(m3)^(__float_as_uint(x3)&0x80000000u));
    float p01=a0*a1, p23=a2*a3, d=p01*p23, rd;
    asm("rcp.approx.f32 %0, %1;" : "=f"(rd) : "f"(d));
    float num = fmaf(fmaf(m0,a1,m1*a0), p23, fmaf(m2,a3,m3*a2)*p01);
    return num * rd;
}
__device__ __forceinline__ float dot8(float4 aa, float4 ab, float4 ba, float4 bb, float acc) {
    acc = fmaf(aa.x, ba.x, acc); acc = fmaf(aa.y, ba.y, acc);
    acc = fmaf(aa.z, ba.z, acc); acc = fmaf(aa.w, ba.w, acc);
    acc = fmaf(ab.x, bb.x, acc); acc = fmaf(ab.y, bb.y, acc);
    acc = fmaf(ab.z, bb.z, acc); acc = fmaf(ab.w, bb.w, acc);
    return acc;
}

// grid-wide barrier (all NBLK blocks co-resident)
__device__ __forceinline__ void gbar() {
    __syncthreads();
    if (threadIdx.x == 0) {
        unsigned old = g_gen;
        __threadfence();
        if (atomicAdd(&g_cnt, 1u) == NBLK - 1u) {
            g_cnt = 0u;
            __threadfence();
            g_gen = old + 1u;
        } else {
            while (g_gen == old) { }
            __threadfence();
        }
    }
    __syncthreads();
}

// ---------------- precompute kernels ----------------
__global__ void k_prep(const float* __restrict__ W_ih1,
                       const float* __restrict__ W_ih2,
                       const float* __restrict__ W_q,
                       const float* __restrict__ b_ih1) {
    int i = blockIdx.x * 256 + threadIdx.x;    // 768 blocks -> 196608
    if (i < Hh*H3) {
        int k = i / H3, j = i % H3;
        g_W1T[i] = W_ih1[j*257 + k];
        int kk  = i & 255;
        int jj  = (i >> 8) % 192;
        int ctc = i / (192*256);
        int gate = jj / 64;
        int col  = ctc*64 + (jj & 63);
        g_W2P[i] = W_ih2[(gate*256 + col)*256 + kk];
    }
    if (i < Hh*Hh) {
        int j = i >> 8, k = i & 255;
        g_WqT[i] = W_q[k*256 + j];
    }
    if (i < H3) {
        float wd = W_ih1[i*257 + 256];
        g_wD[i] = wd;
        g_bias0[i] = b_ih1[i] + wd;
    }
}

__global__ void k_mean(const float* __restrict__ enc) {
    int b = blockIdx.x, h = threadIdx.x;
    float s = 0.f;
    for (int n = 0; n < Nn; n++) s += enc[(b*Nn + n)*Hh + h];
    g_mean[b*Hh + h] = s / (float)Nn;
}

template<int BM, int BN, int TM, int TN>
__global__ __launch_bounds__(256)
void k_sgemm(const float* __restrict__ A, const float* __restrict__ Bm,
             const float* __restrict__ bias, float* __restrict__ C,
             int M, int N, int K) {
    const int BK = 16;
    __shared__ float As[BK][BM];
    __shared__ float Bs[BK][BN];
    int tid = threadIdx.x;
    int tx = tid % (BN/TN), ty = tid / (BN/TN);
    int m0 = blockIdx.y * BM, n0 = blockIdx.x * BN;
    float acc[TM][TN];
#pragma unroll
    for (int i = 0; i < TM; i++)
#pragma unroll
        for (int j = 0; j < TN; j++) acc[i][j] = 0.f;
    for (int k0 = 0; k0 < K; k0 += BK) {
#pragma unroll
        for (int r = 0; r < (BM*BK)/1024; r++) {
            int idx = tid + r*256, mm = idx/(BK/4), kk4 = idx%(BK/4);
            float4 a = *(const float4*)&A[(size_t)(m0+mm)*K + k0 + kk4*4];
            As[kk4*4+0][mm]=a.x; As[kk4*4+1][mm]=a.y; As[kk4*4+2][mm]=a.z; As[kk4*4+3][mm]=a.w;
        }
#pragma unroll
        for (int r = 0; r < (BK*BN)/1024; r++) {
            int idx = tid + r*256, kk = idx/(BN/4), nn4 = idx%(BN/4);
            *(float4*)&Bs[kk][nn4*4] = *(const float4*)&Bm[(size_t)(k0+kk)*N + n0 + nn4*4];
        }
        __syncthreads();
#pragma unroll
        for (int kk = 0; kk < BK; kk++) {
            float ra[TM], rb[TN];
#pragma unroll
            for (int i = 0; i < TM; i += 4) *(float4*)&ra[i] = *(float4*)&As[kk][ty*TM+i];
#pragma unroll
            for (int j = 0; j < TN; j += 4) *(float4*)&rb[j] = *(float4*)&Bs[kk][tx*TN+j];
#pragma unroll
            for (int i = 0; i < TM; i++)
#pragma unroll
                for (int j = 0; j < TN; j++) acc[i][j] += ra[i]*rb[j];
        }
        __syncthreads();
    }
#pragma unroll
    for (int i = 0; i < TM; i++) {
        int m = m0 + ty*TM + i;
#pragma unroll
        for (int j = 0; j < TN; j += 4) {
            int n = n0 + tx*TN + j;
            float4 r;
            r.x = acc[i][j+0] + (bias ? bias[n+0] : 0.f);
            r.y = acc[i][j+1] + (bias ? bias[n+1] : 0.f);
            r.z = acc[i][j+2] + (bias ? bias[n+2] : 0.f);
            r.w = acc[i][j+3] + (bias ? bias[n+3] : 0.f);
            *(float4*)&C[(size_t)m*N + n] = r;
        }
    }
}

// ---------------- persistent decode loop: chip-wide phases ----------------
__global__ __launch_bounds__(256, 1)
void k_loop(const float* __restrict__ G,  const float* __restrict__ G0,
            const float* __restrict__ REF,
            const float* __restrict__ W2P, const float* __restrict__ WqT,
            const float* __restrict__ b_hh1,
            const float* __restrict__ b_ih2, const float* __restrict__ b_hh2,
            const float* __restrict__ v,   const float* __restrict__ wD,
            const float* __restrict__ x,
            float* __restrict__ H1, float* __restrict__ H2, float* __restrict__ Q,
            float* __restrict__ out) {
    __shared__ float sh_h[32*256];
    __shared__ float sh_su[8*100];
    __shared__ int   sh_nxt[8];
    __shared__ unsigned char sh_mask[800];
    __shared__ unsigned char sh_pi[800];

    const int tid = threadIdx.x, lane = tid & 31, w = tid >> 5;
    const int bi = blockIdx.x;
    const int b0 = bi * 8;                 // rows for phases A/D
    const int rt = bi >> 2, ct = bi & 3;   // GEMM tile: rows rt*32.., cols ct*64..
    const int tx = tid & 63, ty = tid >> 6;

    for (int i = tid; i < 800; i += 256) sh_mask[i] = 0;

    const float4 v0 = *(const float4*)(v + lane*4);
    const float4 v1 = *(const float4*)(v + 128 + lane*4);

    const int j0 = ct*64 + tx;
    const float bi2r = __ldg(b_ih2 + j0),       bh2r = __ldg(b_hh2 + j0);
    const float bi2z = __ldg(b_ih2 + 256 + j0), bh2z = __ldg(b_hh2 + 256 + j0);
    const float bi2n = __ldg(b_ih2 + 512 + j0), bh2n = __ldg(b_hh2 + 512 + j0);

    const float* Wp  = W2P + (size_t)ct*(192*256);
    const float* Wqp = WqT + (size_t)(ct*64)*256;

    float Dv = 1.0f, ll = 0.0f;
    __syncthreads();

#pragma unroll 1
    for (int t = 0; t < Nn; t++) {
        // ---- A: GRU1 (h=0) -> H1, warp w owns row b0+w ----
        {
            const float* gsrc = (t == 0) ? (G0 + (size_t)(b0 + w)*H3)
                                         : (G + ((size_t)(b0 + w)*Nn + sh_nxt[w])*H3);
#pragma unroll
            for (int c = 0; c < 8; c++) {
                int j = lane + 32*c;
                float gr = __ldg(gsrc+j), gz = __ldg(gsrc+j+256), gn = __ldg(gsrc+j+512);
                if (t > 0) {
                    gr = fmaf(Dv, __ldg(wD+j),     gr);
                    gz = fmaf(Dv, __ldg(wD+j+256), gz);
                    gn = fmaf(Dv, __ldg(wD+j+512), gn);
                }
                float rr = sigmoidf_(gr + __ldg(b_hh1+j));
                float zz = sigmoidf_(gz + __ldg(b_hh1+j+256));
                float nn = fast_tanh(fmaf(rr, __ldg(b_hh1+j+512), gn));
                H1[(size_t)(b0 + w)*Hh + j] = (1.f - zz) * nn;
            }
        }
        gbar();

        // ---- B: GEMM2 tile (32 rows x 64 h2-cols x 3 gates) + fused GRU2 -> H2 ----
        // H1 written by other SMs: read L2-fresh via __ldcg (bypass L1)
        {
            const float4* src = (const float4*)(H1 + (size_t)rt*32*Hh);
            float4* dst = (float4*)sh_h;
#pragma unroll
            for (int i = 0; i < 8; i++) dst[tid + i*256] = __ldcg(src + tid + i*256);
        }
        __syncthreads();
        {
            float acc0[8], acc1[8], acc2[8];
#pragma unroll
            for (int r = 0; r < 8; r++) { acc0[r]=0.f; acc1[r]=0.f; acc2[r]=0.f; }
#pragma unroll 1
            for (int k0 = 0; k0 < 256; k0 += 8) {
                float4 b0a = __ldg((const float4*)(Wp + (size_t)(tx      )*256 + k0));
                float4 b0b = __ldg((const float4*)(Wp + (size_t)(tx      )*256 + k0 + 4));
                float4 b1a = __ldg((const float4*)(Wp + (size_t)(tx + 64 )*256 + k0));
                float4 b1b = __ldg((const float4*)(Wp + (size_t)(tx + 64 )*256 + k0 + 4));
                float4 b2a = __ldg((const float4*)(Wp + (size_t)(tx + 128)*256 + k0));
                float4 b2b = __ldg((const float4*)(Wp + (size_t)(tx + 128)*256 + k0 + 4));
#pragma unroll
                for (int r = 0; r < 8; r++) {
                    const float* hrow = sh_h + (ty*8 + r)*256 + k0;
                    float4 aa = *(const float4*)hrow;
                    float4 ab = *(const float4*)(hrow + 4);
                    acc0[r] = dot8(aa, ab, b0a, b0b, acc0[r]);
                    acc1[r] = dot8(aa, ab, b1a, b1b, acc1[r]);
                    acc2[r] = dot8(aa, ab, b2a, b2b, acc2[r]);
                }
            }
#pragma unroll
            for (int r = 0; r < 8; r++) {
                float rr = sigmoidf_((acc0[r] + bi2r) + bh2r);
                float zz = sigmoidf_((acc1[r] + bi2z) + bh2z);
                float nn = fast_tanh(fmaf(rr, bh2n, acc2[r] + bi2n));
                H2[(size_t)(rt*32 + ty*8 + r)*Hh + ct*64 + tx] = (1.f - zz) * nn;
            }
        }
        gbar();

        // ---- C: GEMM3 tile (32 rows x 64 cols) -> Q ----
        {
            const float4* src = (const float4*)(H2 + (size_t)rt*32*Hh);
            float4* dst = (float4*)sh_h;
#pragma unroll
            for (int i = 0; i < 8; i++) dst[tid + i*256] = __ldcg(src + tid + i*256);
        }
        __syncthreads();
        {
            float qacc[8];
#pragma unroll
            for (int r = 0; r < 8; r++) qacc[r] = 0.f;
#pragma unroll 1
            for (int k0 = 0; k0 < 256; k0 += 8) {
                float4 ba = __ldg((const float4*)(Wqp + (size_t)tx*256 + k0));
                float4 bb = __ldg((const float4*)(Wqp + (size_t)tx*256 + k0 + 4));
#pragma unroll
                for (int r = 0; r < 8; r++) {
                    const float* hrow = sh_h + (ty*8 + r)*256 + k0;
                    float4 aa = *(const float4*)hrow;
                    float4 ab = *(const float4*)(hrow + 4);
                    qacc[r] = dot8(aa, ab, ba, bb, qacc[r]);
                }
            }
#pragma unroll
            for (int r = 0; r < 8; r++)
                Q[(size_t)(rt*32 + ty*8 + r)*Hh + ct*64 + tx] = qacc[r];
        }
        for (int i = tid; i < 800; i += 256) sh_su[i] = -1000000000.0f;
        gbar();

        // ---- D: attention / argmax / log-softmax / state, warp w owns row b0+w ----
        {
            const int R = b0 + w;
            float4 q0 = __ldcg((const float4*)(Q + (size_t)R*Hh) + lane);
            float4 q1 = __ldcg((const float4*)(Q + (size_t)R*Hh) + 32 + lane);
            const float4* refrow = (const float4*)(REF + (size_t)R*Nn*Hh);
#pragma unroll 1
            for (int n = 0; n < Nn; n++) {
                if (sh_mask[w*100 + n]) continue;
                float4 r0 = __ldg(refrow + n*64 + lane);
                float4 r1 = __ldg(refrow + n*64 + 32 + lane);
                float s = tanh4dot(q0, r0, v0) + tanh4dot(q1, r1, v1);
#pragma unroll
                for (int o = 16; o; o >>= 1) s += __shfl_xor_sync(~0u, s, o);
                if (lane == 0) sh_su[w*100 + n] = 10.f * fast_tanh(s);
            }
            __syncwarp();
            float best = -INFINITY; int bidx = 0x7fffffff;
            for (int n = lane; n < Nn; n += 32) {
                float u = sh_su[w*100 + n];
                if (u > best) { best = u; bidx = n; }
            }
#pragma unroll
            for (int o = 16; o; o >>= 1) {
                float ov = __shfl_xor_sync(~0u, best, o);
                int   oi = __shfl_xor_sync(~0u, bidx, o);
                if (ov > best || (ov == best && oi < bidx)) { best = ov; bidx = oi; }
            }
            float se = 0.f;
            for (int n = lane; n < Nn; n += 32) se += __expf(sh_su[w*100 + n] - best);
#pragma unroll
            for (int o = 16; o; o >>= 1) se += __shfl_xor_sync(~0u, se, o);
            ll += -__logf(se);
            if (lane == 0) {
                sh_nxt[w] = bidx;
                sh_mask[w*100 + bidx] = 1;
                sh_pi[w*100 + t] = (unsigned char)bidx;
            }
            __syncwarp();
        }
        Dv -= 0.01f;
    }

    // ---- tour cost + output, warp w owns row b0+w ----
    {
        float cs = 0.f;
        const float* xb = x + (size_t)(b0 + w)*Nn*2;
        for (int tt = lane; tt < Nn; tt += 32) {
            int a  = sh_pi[w*100 + tt];
            int cc = sh_pi[w*100 + ((tt == Nn-1) ? 0 : tt+1)];
            float dx = __ldg(xb + a*2)     - __ldg(xb + cc*2);
            float dy = __ldg(xb + a*2 + 1) - __ldg(xb + cc*2 + 1);
            cs += sqrtf(dx*dx + dy*dy);
        }
#pragma unroll
        for (int o = 16; o; o >>= 1) cs += __shfl_xor_sync(~0u, cs, o);
        if (lane == 0) { out[b0 + w] = cs; out[Bsz + b0 + w] = ll; }
    }
}

// ---------------- launcher ----------------
extern "C" void kernel_launch(void* const* d_in, const int* in_sizes, int n_in,
                              void* d_out, int out_size) {
    const float* x     = (const float*)d_in[0];
    const float* enc   = (const float*)d_in[1];
    const float* W_ih1 = (const float*)d_in[2];
    const float* b_ih1 = (const float*)d_in[4];
    const float* b_hh1 = (const float*)d_in[5];
    const float* W_ih2 = (const float*)d_in[6];
    const float* b_ih2 = (const float*)d_in[8];
    const float* b_hh2 = (const float*)d_in[9];
    const float* W_q   = (const float*)d_in[10];
    const float* W_ref = (const float*)d_in[11];
    const float* v     = (const float*)d_in[12];
    float* out = (float*)d_out;

    float *G, *REF, *G0, *MEAN, *W1T, *W2P, *WqT, *BIAS0, *WD, *H1, *H2, *Q;
    cudaGetSymbolAddress((void**)&G,    g_G);
    cudaGetSymbolAddress((void**)&REF,  g_ref);
    cudaGetSymbolAddress((void**)&G0,   g_G0);
    cudaGetSymbolAddress((void**)&MEAN, g_mean);
    cudaGetSymbolAddress((void**)&W1T,  g_W1T);
    cudaGetSymbolAddress((void**)&W2P,  g_W2P);
    cudaGetSymbolAddress((void**)&WqT,  g_WqT);
    cudaGetSymbolAddress((void**)&BIAS0,g_bias0);
    cudaGetSymbolAddress((void**)&WD,   g_wD);
    cudaGetSymbolAddress((void**)&H1,   g_h1);
    cudaGetSymbolAddress((void**)&H2,   g_h2);
    cudaGetSymbolAddress((void**)&Q,    g_q);

    k_prep<<<768, 256>>>(W_ih1, W_ih2, W_q, b_ih1);
    k_mean<<<Bsz, 256>>>(enc);
    k_sgemm<128,128,8,8><<<dim3(H3/128, (Bsz*Nn)/128), 256>>>(enc, W1T, b_ih1, G, Bsz*Nn, H3, Hh);
    k_sgemm<128,128,8,8><<<dim3(Hh/128, (Bsz*Nn)/128), 256>>>(enc, W_ref, nullptr, REF, Bsz*Nn, Hh, Hh);
    k_sgemm<64,64,4,4><<<dim3(H3/64, Bsz/64), 256>>>(MEAN, W1T, BIAS0, G0, Bsz, H3, Hh);
    k_loop<<<NBLK, 256>>>(G, G0, REF, W2P, WqT, b_hh1, b_ih2, b_hh2, v, WD, x,
                          H1, H2, Q, out);
}

// round 6
// speedup vs baseline: 1.7615x; 1.7615x over previous
#include <cuda_runtime.h>
#include <math.h>

#define Bsz 1024
#define Nn  100
#define Hh  256
#define H3  768
#define NBLK 128
#define NT  512

// ---------------- static device scratch ----------------
__device__ float g_G[Bsz*Nn*H3];      // enc @ W1T + b_ih1
__device__ float g_ref[Bsz*Nn*Hh];    // enc @ W_ref
__device__ float g_G0[Bsz*H3];
__device__ float g_mean[Bsz*Hh];
__device__ float g_W1T[Hh*H3];        // [k][j] for precompute GEMM
__device__ float g_W2P[H3*Hh];        // packed: [tk][kk4][j][c]  (8 x 8 x 768 x 4)
__device__ float g_WqP[Hh*Hh];        // packed: [tk][kk4][j][c]  (8 x 8 x 256 x 4)
__device__ float g_bias0[H3];
__device__ float g_wD[H3];

// ---------------- math helpers ----------------
__device__ __forceinline__ float fast_tanh(float x) {
    float ax = fabsf(x);
    float e  = __expf(-2.0f * ax);
    float t  = __fdividef(1.0f - e, 1.0f + e);
    return copysignf(t, x);
}
__device__ __forceinline__ float sigmoidf_(float x) {
    return __fdividef(1.0f, 1.0f + __expf(-x));
}
__device__ __forceinline__ float tanh4dot(float4 q, float4 r, float4 v) {
    const float C = -2.8853900817779268f;   // -2*log2(e)
    float x0=q.x+r.x, x1=q.y+r.y, x2=q.z+r.z, x3=q.w+r.w;
    float e0=exp2f(fabsf(x0)*C), e1=exp2f(fabsf(x1)*C);
    float e2=exp2f(fabsf(x2)*C), e3=exp2f(fabsf(x3)*C);
    float a0=1.f+e0, a1=1.f+e1, a2=1.f+e2, a3=1.f+e3;
    float m0=(1.f-e0)*v.x, m1=(1.f-e1)*v.y, m2=(1.f-e2)*v.z, m3=(1.f-e3)*v.w;
    m0=__uint_as_float(__float_as_uint(m0)^(__float_as_uint(x0)&0x80000000u));
    m1=__uint_as_float(__float_as_uint(m1)^(__float_as_uint(x1)&0x80000000u));
    m2=__uint_as_float(__float_as_uint(m2)^(__float_as_uint(x2)&0x80000000u));
    m3=__uint_as_float(__float_as_uint(m3)^(__float_as_uint(x3)&0x80000000u));
    float p01=a0*a1, p23=a2*a3, d=p01*p23, rd;
    asm("rcp.approx.f32 %0, %1;" : "=f"(rd) : "f"(d));
    float num = fmaf(fmaf(m0,a1,m1*a0), p23, fmaf(m2,a3,m3*a2)*p01);
    return num * rd;
}
__device__ __forceinline__ float dot4(float4 a, float4 b, float acc) {
    acc = fmaf(a.x, b.x, acc); acc = fmaf(a.y, b.y, acc);
    acc = fmaf(a.z, b.z, acc); acc = fmaf(a.w, b.w, acc);
    return acc;
}
__device__ __forceinline__ void cp16(float* dst, const float* src) {
    unsigned d = (unsigned)__cvta_generic_to_shared(dst);
    asm volatile("cp.async.cg.shared.global [%0], [%1], 16;" :: "r"(d), "l"(src) : "memory");
}
#define CP_COMMIT() asm volatile("cp.async.commit_group;")
#define CP_WAIT0()  asm volatile("cp.async.wait_group 0;")

// ---------------- precompute kernels ----------------
__global__ void k_prep(const float* __restrict__ W_ih1,
                       const float* __restrict__ W_ih2,
                       const float* __restrict__ W_q,
                       const float* __restrict__ b_ih1) {
    int i = blockIdx.x * 256 + threadIdx.x;    // 768 blocks -> 196608
    if (i < Hh*H3) {
        int k = i / H3, j = i % H3;
        g_W1T[i] = W_ih1[j*257 + k];
        // W2P packed: tmp = i>>2 = tk*6144 + kk4*768 + j ; c = i&3
        int c = i & 3, tmp = i >> 2;
        int jj = tmp % 768, kk4 = (tmp / 768) & 7, tk = tmp / 6144;
        int kk = tk*32 + kk4*4 + c;
        g_W2P[i] = W_ih2[jj*256 + kk];
    }
    if (i < Hh*Hh) {
        // WqP packed: tmp = i>>2 = tk*2048 + kk4*256 + j ; c = i&3
        int c = i & 3, tmp = i >> 2;
        int jj = tmp & 255, kk4 = (tmp >> 8) & 7, tk = tmp >> 11;
        int kk = tk*32 + kk4*4 + c;
        g_WqP[i] = W_q[kk*256 + jj];
    }
    if (i < H3) {
        float wd = W_ih1[i*257 + 256];
        g_wD[i] = wd;
        g_bias0[i] = b_ih1[i] + wd;
    }
}

__global__ void k_mean(const float* __restrict__ enc) {
    int b = blockIdx.x, h = threadIdx.x;
    float s = 0.f;
    for (int n = 0; n < Nn; n++) s += enc[(b*Nn + n)*Hh + h];
    g_mean[b*Hh + h] = s / (float)Nn;
}

template<int BM, int BN, int TM, int TN>
__global__ __launch_bounds__(256)
void k_sgemm(const float* __restrict__ A, const float* __restrict__ Bm,
             const float* __restrict__ bias, float* __restrict__ C,
             int M, int N, int K) {
    const int BK = 16;
    __shared__ float As[BK][BM];
    __shared__ float Bs[BK][BN];
    int tid = threadIdx.x;
    int tx = tid % (BN/TN), ty = tid / (BN/TN);
    int m0 = blockIdx.y * BM, n0 = blockIdx.x * BN;
    float acc[TM][TN];
#pragma unroll
    for (int i = 0; i < TM; i++)
#pragma unroll
        for (int j = 0; j < TN; j++) acc[i][j] = 0.f;
    for (int k0 = 0; k0 < K; k0 += BK) {
#pragma unroll
        for (int r = 0; r < (BM*BK)/1024; r++) {
            int idx = tid + r*256, mm = idx/(BK/4), kk4 = idx%(BK/4);
            float4 a = *(const float4*)&A[(size_t)(m0+mm)*K + k0 + kk4*4];
            As[kk4*4+0][mm]=a.x; As[kk4*4+1][mm]=a.y; As[kk4*4+2][mm]=a.z; As[kk4*4+3][mm]=a.w;
        }
#pragma unroll
        for (int r = 0; r < (BK*BN)/1024; r++) {
            int idx = tid + r*256, kk = idx/(BN/4), nn4 = idx%(BN/4);
            *(float4*)&Bs[kk][nn4*4] = *(const float4*)&Bm[(size_t)(k0+kk)*N + n0 + nn4*4];
        }
        __syncthreads();
#pragma unroll
        for (int kk = 0; kk < BK; kk++) {
            float ra[TM], rb[TN];
#pragma unroll
            for (int i = 0; i < TM; i += 4) *(float4*)&ra[i] = *(float4*)&As[kk][ty*TM+i];
#pragma unroll
            for (int j = 0; j < TN; j += 4) *(float4*)&rb[j] = *(float4*)&Bs[kk][tx*TN+j];
#pragma unroll
            for (int i = 0; i < TM; i++)
#pragma unroll
                for (int j = 0; j < TN; j++) acc[i][j] += ra[i]*rb[j];
        }
        __syncthreads();
    }
#pragma unroll
    for (int i = 0; i < TM; i++) {
        int m = m0 + ty*TM + i;
#pragma unroll
        for (int j = 0; j < TN; j += 4) {
            int n = n0 + tx*TN + j;
            float4 r;
            r.x = acc[i][j+0] + (bias ? bias[n+0] : 0.f);
            r.y = acc[i][j+1] + (bias ? bias[n+1] : 0.f);
            r.z = acc[i][j+2] + (bias ? bias[n+2] : 0.f);
            r.w = acc[i][j+3] + (bias ? bias[n+3] : 0.f);
            *(float4*)&C[(size_t)m*N + n] = r;
        }
    }
}

// ---------------- monolithic block-local decode loop ----------------
// 128 blocks x 512 threads; block owns 8 batch rows; all state in smem.
// smem: shB 2x24576 | h1 2048 | h2 2048 | q 2048 | v 256 | su 800 | nxt 8i | mask 800B | pi 800B
#define SMEM_BYTES ((49152 + 2048*3 + 256 + 800)*4 + 8*4 + 800 + 800)

__global__ __launch_bounds__(NT, 1)
void k_loop(const float* __restrict__ G,  const float* __restrict__ G0,
            const float* __restrict__ REF,
            const float* __restrict__ W2P, const float* __restrict__ WqP,
            const float* __restrict__ b_hh1,
            const float* __restrict__ b_ih2, const float* __restrict__ b_hh2,
            const float* __restrict__ v,   const float* __restrict__ wD,
            const float* __restrict__ x,   float* __restrict__ out) {
    extern __shared__ float sm[];
    float* shB   = sm;                    // 2 x 24576
    float* sh_h1 = sm + 49152;
    float* sh_h2 = sh_h1 + 2048;
    float* sh_q  = sh_h2 + 2048;
    float* sh_v  = sh_q + 2048;
    float* sh_su = sh_v + 256;
    int*   sh_nxt = (int*)(sh_su + 800);
    unsigned char* sh_mask = (unsigned char*)(sh_nxt + 8);
    unsigned char* sh_pi   = sh_mask + 800;

    const int tid = threadIdx.x, lane = tid & 31, w = tid >> 5;
    const int b0 = blockIdx.x * 8;
    const int j0 = tid & 255, rh = tid >> 8;   // GEMM mapping: triplet j0, rows rh*4..rh*4+3

    for (int i = tid; i < 800; i += NT) sh_mask[i] = 0;
    if (tid < 256) sh_v[tid] = __ldg(v + tid);

    const float bi2r = __ldg(b_ih2 + j0),       bh2r = __ldg(b_hh2 + j0);
    const float bi2z = __ldg(b_ih2 + 256 + j0), bh2z = __ldg(b_hh2 + 256 + j0);
    const float bi2n = __ldg(b_ih2 + 512 + j0), bh2n = __ldg(b_hh2 + 512 + j0);

    // prefetch W2P tile0 -> buf0 (24576 floats, 12 float4/thread)
#pragma unroll
    for (int p = 0; p < 12; p++) { int e = tid + p*NT; cp16(shB + e*4, W2P + e*4); }
    CP_COMMIT();
    __syncthreads();

    float Dv = 1.0f, ll = 0.0f;

#pragma unroll 1
    for (int t = 0; t < Nn; t++) {
        // ---- A: GRU1 (h=0) -> sh_h1 ----
#pragma unroll
        for (int c = 0; c < 4; c++) {
            int idx = tid + c*NT;              // 2048 outputs
            int row = idx >> 8, j = idx & 255;
            const float* gsrc = (t == 0) ? (G0 + (size_t)(b0 + row)*H3)
                                         : (G + ((size_t)(b0 + row)*Nn + sh_nxt[row])*H3);
            float gr = __ldg(gsrc+j), gz = __ldg(gsrc+j+256), gn = __ldg(gsrc+j+512);
            if (t > 0) {
                gr = fmaf(Dv, __ldg(wD+j),     gr);
                gz = fmaf(Dv, __ldg(wD+j+256), gz);
                gn = fmaf(Dv, __ldg(wD+j+512), gn);
            }
            float rr = sigmoidf_(gr + __ldg(b_hh1+j));
            float zz = sigmoidf_(gz + __ldg(b_hh1+j+256));
            float nn = fast_tanh(fmaf(rr, __ldg(b_hh1+j+512), gn));
            sh_h1[idx] = (1.f - zz) * nn;
        }
        __syncthreads();

        // ---- B: GEMM2 (gi2 = h1 @ W2T) + fused GRU2 -> sh_h2 ----
        {
            float acc0[4], acc1[4], acc2[4];
#pragma unroll
            for (int r = 0; r < 4; r++) { acc0[r]=0.f; acc1[r]=0.f; acc2[r]=0.f; }
#pragma unroll 1
            for (int tile = 0; tile < 8; tile++) {
                CP_WAIT0();
                __syncthreads();
                if (tile < 7) {
                    const float* src = W2P + (tile+1)*24576;
                    float* dst = shB + ((tile+1)&1)*24576;
#pragma unroll
                    for (int p = 0; p < 12; p++) { int e = tid + p*NT; cp16(dst + e*4, src + e*4); }
                    CP_COMMIT();
                } else {
                    // buf0 free (last read at tile 6): prefetch WqP tile0
#pragma unroll
                    for (int p = 0; p < 4; p++) { int e = tid + p*NT; cp16(shB + e*4, WqP + e*4); }
                    CP_COMMIT();
                }
                const float* Bt = shB + (tile&1)*24576;
#pragma unroll
                for (int kk4 = 0; kk4 < 8; kk4++) {
                    const float* bp = Bt + kk4*3072 + j0*4;
                    float4 bb0 = *(const float4*)bp;
                    float4 bb1 = *(const float4*)(bp + 1024);
                    float4 bb2 = *(const float4*)(bp + 2048);
#pragma unroll
                    for (int r = 0; r < 4; r++) {
                        float4 a = *(const float4*)(sh_h1 + (rh*4+r)*256 + tile*32 + kk4*4);
                        acc0[r] = dot4(a, bb0, acc0[r]);
                        acc1[r] = dot4(a, bb1, acc1[r]);
                        acc2[r] = dot4(a, bb2, acc2[r]);
                    }
                }
            }
#pragma unroll
            for (int r = 0; r < 4; r++) {
                float rr = sigmoidf_((acc0[r] + bi2r) + bh2r);
                float zz = sigmoidf_((acc1[r] + bi2z) + bh2z);
                float nn = fast_tanh(fmaf(rr, bh2n, acc2[r] + bi2n));
                sh_h2[(rh*4+r)*256 + j0] = (1.f - zz) * nn;
            }
        }
        __syncthreads();

        // ---- C: GEMM3 (q = h2 @ Wq) -> sh_q ----
        {
            float qa[4];
#pragma unroll
            for (int r = 0; r < 4; r++) qa[r] = 0.f;
#pragma unroll 1
            for (int tile = 0; tile < 8; tile++) {
                CP_WAIT0();
                __syncthreads();
                if (tile < 7) {
                    const float* src = WqP + (tile+1)*8192;
                    float* dst = shB + ((tile+1)&1)*24576;
#pragma unroll
                    for (int p = 0; p < 4; p++) { int e = tid + p*NT; cp16(dst + e*4, src + e*4); }
                    CP_COMMIT();
                } else {
                    // buf0 free: prefetch next step's W2P tile0
#pragma unroll
                    for (int p = 0; p < 12; p++) { int e = tid + p*NT; cp16(shB + e*4, W2P + e*4); }
                    CP_COMMIT();
                }
                const float* Bt = shB + (tile&1)*24576;
#pragma unroll
                for (int kk4 = 0; kk4 < 8; kk4++) {
                    float4 bb = *(const float4*)(Bt + kk4*1024 + j0*4);
#pragma unroll
                    for (int r = 0; r < 4; r++) {
                        float4 a = *(const float4*)(sh_h2 + (rh*4+r)*256 + tile*32 + kk4*4);
                        qa[r] = dot4(a, bb, qa[r]);
                    }
                }
            }
#pragma unroll
            for (int r = 0; r < 4; r++) sh_q[(rh*4+r)*256 + j0] = qa[r];
        }
        for (int i = tid; i < 800; i += NT) sh_su[i] = -1000000000.0f;
        __syncthreads();

        // ---- D: attention, 2 warps per row (parity-split n) ----
        {
            const int w2 = w >> 1, par = w & 1;
            const int R = b0 + w2;
            float4 q0 = *(const float4*)(sh_q + w2*256 + lane*4);
            float4 q1 = *(const float4*)(sh_q + w2*256 + 128 + lane*4);
            float4 v0 = *(const float4*)(sh_v + lane*4);
            float4 v1 = *(const float4*)(sh_v + 128 + lane*4);
            const float4* refrow = (const float4*)(REF + (size_t)R*Nn*Hh);
#pragma unroll 1
            for (int n = par; n < Nn; n += 2) {
                if (sh_mask[w2*100 + n]) continue;
                float4 r0 = __ldg(refrow + n*64 + lane);
                float4 r1 = __ldg(refrow + n*64 + 32 + lane);
                float s = tanh4dot(q0, r0, v0) + tanh4dot(q1, r1, v1);
#pragma unroll
                for (int o = 16; o; o >>= 1) s += __shfl_xor_sync(~0u, s, o);
                if (lane == 0) sh_su[w2*100 + n] = 10.f * fast_tanh(s);
            }
        }
        __syncthreads();
        // argmax / log-softmax / state: warp w handles row w (w < 8)
        if (w < 8) {
            float best = -INFINITY; int bidx = 0x7fffffff;
            for (int n = lane; n < Nn; n += 32) {
                float u = sh_su[w*100 + n];
                if (u > best) { best = u; bidx = n; }
            }
#pragma unroll
            for (int o = 16; o; o >>= 1) {
                float ov = __shfl_xor_sync(~0u, best, o);
                int   oi = __shfl_xor_sync(~0u, bidx, o);
                if (ov > best || (ov == best && oi < bidx)) { best = ov; bidx = oi; }
            }
            float se = 0.f;
            for (int n = lane; n < Nn; n += 32) se += __expf(sh_su[w*100 + n] - best);
#pragma unroll
            for (int o = 16; o; o >>= 1) se += __shfl_xor_sync(~0u, se, o);
            ll += -__logf(se);
            if (lane == 0) {
                sh_nxt[w] = bidx;
                sh_mask[w*100 + bidx] = 1;
                sh_pi[w*100 + t] = (unsigned char)bidx;
            }
        }
        __syncthreads();
        Dv -= 0.01f;
    }
    CP_WAIT0();
    __syncthreads();

    // ---- tour cost + output: warp w handles row w (w < 8) ----
    if (w < 8) {
        float cs = 0.f;
        const float* xb = x + (size_t)(b0 + w)*Nn*2;
        for (int tt = lane; tt < Nn; tt += 32) {
            int a  = sh_pi[w*100 + tt];
            int cc = sh_pi[w*100 + ((tt == Nn-1) ? 0 : tt+1)];
            float dx = __ldg(xb + a*2)     - __ldg(xb + cc*2);
            float dy = __ldg(xb + a*2 + 1) - __ldg(xb + cc*2 + 1);
            cs += sqrtf(dx*dx + dy*dy);
        }
#pragma unroll
        for (int o = 16; o; o >>= 1) cs += __shfl_xor_sync(~0u, cs, o);
        if (lane == 0) { out[b0 + w] = cs; out[Bsz + b0 + w] = ll; }
    }
}

// ---------------- launcher ----------------
extern "C" void kernel_launch(void* const* d_in, const int* in_sizes, int n_in,
                              void* d_out, int out_size) {
    const float* x     = (const float*)d_in[0];
    const float* enc   = (const float*)d_in[1];
    const float* W_ih1 = (const float*)d_in[2];
    const float* b_ih1 = (const float*)d_in[4];
    const float* b_hh1 = (const float*)d_in[5];
    const float* W_ih2 = (const float*)d_in[6];
    const float* b_ih2 = (const float*)d_in[8];
    const float* b_hh2 = (const float*)d_in[9];
    const float* W_q   = (const float*)d_in[10];
    const float* W_ref = (const float*)d_in[11];
    const float* v     = (const float*)d_in[12];
    float* out = (float*)d_out;

    float *G, *REF, *G0, *MEAN, *W1T, *W2P, *WqP, *BIAS0, *WD;
    cudaGetSymbolAddress((void**)&G,    g_G);
    cudaGetSymbolAddress((void**)&REF,  g_ref);
    cudaGetSymbolAddress((void**)&G0,   g_G0);
    cudaGetSymbolAddress((void**)&MEAN, g_mean);
    cudaGetSymbolAddress((void**)&W1T,  g_W1T);
    cudaGetSymbolAddress((void**)&W2P,  g_W2P);
    cudaGetSymbolAddress((void**)&WqP,  g_WqP);
    cudaGetSymbolAddress((void**)&BIAS0,g_bias0);
    cudaGetSymbolAddress((void**)&WD,   g_wD);

    cudaFuncSetAttribute(k_loop, cudaFuncAttributeMaxDynamicSharedMemorySize, SMEM_BYTES);

    k_prep<<<768, 256>>>(W_ih1, W_ih2, W_q, b_ih1);
    k_mean<<<Bsz, 256>>>(enc);
    k_sgemm<128,128,8,8><<<dim3(H3/128, (Bsz*Nn)/128), 256>>>(enc, W1T, b_ih1, G, Bsz*Nn, H3, Hh);
    k_sgemm<128,128,8,8><<<dim3(Hh/128, (Bsz*Nn)/128), 256>>>(enc, W_ref, nullptr, REF, Bsz*Nn, Hh, Hh);
    k_sgemm<64,64,4,4><<<dim3(H3/64, Bsz/64), 256>>>(MEAN, W1T, BIAS0, G0, Bsz, H3, Hh);
    k_loop<<<NBLK, NT, SMEM_BYTES>>>(G, G0, REF, W2P, WqP, b_hh1, b_ih2, b_hh2, v, WD, x, out);
}